// round 12
// baseline (speedup 1.0000x reference)
#include <cuda_runtime.h>
#include <cuda_fp16.h>

#define R0_   128
#define R1_   512
#define HW0   (R0_ * R0_)
#define HW1   (R1_ * R1_)

// All planes as duplicated y-pair blocks:
//   copy P (P=0,1), block k in [0,R/2), column x:
//     128B block = 32 x half2( v(row 2k+P, x), v(row min(2k+P+1,R-1), x) )
__device__ __half2 g_xy0[2 * HW0 * 16];
__device__ __half2 g_xz0[2 * HW0 * 16];
__device__ __half2 g_yz0[2 * HW0 * 16];
__device__ __half2 g_xy1[2 * HW1 * 16];
__device__ __half2 g_xz1[2 * HW1 * 16];
__device__ __half2 g_yz1[2 * HW1 * 16];

#define KT0 ((R0_ / 2) * (R0_ / 64))      // 128 blocks per coarse plane
#define KT1 ((R1_ / 2) * (R1_ / 64))      // 2048 blocks per fine plane
#define KT_ALL (3 * KT0 + 3 * KT1)

__global__ void transpose_all_kernel(const float* __restrict__ in0,
                                     const float* __restrict__ in1,
                                     const float* __restrict__ in2,
                                     const float* __restrict__ in3,
                                     const float* __restrict__ in4,
                                     const float* __restrict__ in5) {
    __shared__ float t0[32][65], t1[32][65], t2[32][65];
    int bid = blockIdx.x;
    int tx = threadIdx.x, ty = threadIdx.y;

    const float* in;
    __half2* out;
    int W, kidx;
    if (bid < 3 * KT0) {
        int plane = bid / KT0;
        kidx = bid % KT0;
        W = R0_;
        in  = plane == 0 ? in0 : (plane == 1 ? in1 : in2);
        out = plane == 0 ? g_xy0 : (plane == 1 ? g_xz0 : g_yz0);
    } else {
        int b = bid - 3 * KT0;
        int plane = b / KT1;
        kidx = b % KT1;
        W = R1_;
        in  = plane == 0 ? in3 : (plane == 1 ? in4 : in5);
        out = plane == 0 ? g_xy1 : (plane == 1 ? g_xz1 : g_yz1);
    }
    int HW = W * W;
    int xtiles = W / 64;
    int k = kidx / xtiles;
    int xbase = (kidx % xtiles) * 64;
    int r0 = 2 * k, r1 = 2 * k + 1, r2 = min(2 * k + 2, W - 1);

#pragma unroll
    for (int cc = 0; cc < 32; cc += 8) {
        int c = cc + ty;
        const float2* p0 = (const float2*)(in + (long)c * HW + (long)r0 * W + xbase);
        const float2* p1 = (const float2*)(in + (long)c * HW + (long)r1 * W + xbase);
        const float2* p2 = (const float2*)(in + (long)c * HW + (long)r2 * W + xbase);
        float2 v0 = p0[tx], v1 = p1[tx], v2 = p2[tx];
        t0[c][2 * tx] = v0.x; t0[c][2 * tx + 1] = v0.y;
        t1[c][2 * tx] = v1.x; t1[c][2 * tx + 1] = v1.y;
        t2[c][2 * tx] = v2.x; t2[c][2 * tx + 1] = v2.y;
    }
    __syncthreads();

    long copyB = (long)(W / 2) * W * 32;
#pragma unroll
    for (int xx = 0; xx < 64; xx += 8) {
        int x = xx + ty;
        long ia = ((long)k * W + xbase + x) * 32 + tx;
        out[ia]         = __floats2half2_rn(t0[tx][x], t1[tx][x]);
        out[copyB + ia] = __floats2half2_rn(t1[tx][x], t2[tx][x]);
    }
}

// Sample one plane for 8 channels; thread t (0..3) owns channels [8t, 8t+8).
// x-lerp in half2 SIMD (lanes = (y0,y1)), y-lerp + accumulation in fp32.
// 32-bit index math. Per corner block the thread loads 2 consecutive uint4.
template <int R>
__device__ __forceinline__ void sample_plane(const uint4* __restrict__ plane,
                                             float gx, float gy, int t,
                                             float acc[8]) {
    const float s = 0.5f * (float)(R - 1);
    float ix = fminf(fmaxf((gx + 1.0f) * s, 0.0f), (float)(R - 1));
    float iy = fminf(fmaxf((gy + 1.0f) * s, 0.0f), (float)(R - 1));
    int x0 = min((int)ix, R - 2);
    int y0 = min((int)iy, R - 2);
    float wx = ix - (float)x0;
    float wy = iy - (float)y0;

    int par = y0 & 1;
    int k   = y0 >> 1;
    int idx = ((par * (R / 2) + k) * R + x0) * 8 + 2 * t;

    uint4 A0 = __ldg(plane + idx);         // x0, channels [8t,8t+4)
    uint4 A1 = __ldg(plane + idx + 1);     // x0, channels [8t+4,8t+8)
    uint4 B0 = __ldg(plane + idx + 8);     // x1
    uint4 B1 = __ldg(plane + idx + 9);
    const __half2* a0 = (const __half2*)&A0;
    const __half2* a1 = (const __half2*)&A1;
    const __half2* b0 = (const __half2*)&B0;
    const __half2* b1 = (const __half2*)&B1;

    __half2 wx2 = __float2half2_rn(wx);
#pragma unroll
    for (int c = 0; c < 4; c++) {
        __half2 m0 = __hfma2(wx2, __hsub2(b0[c], a0[c]), a0[c]);
        __half2 m1 = __hfma2(wx2, __hsub2(b1[c], a1[c]), a1[c]);
        float2 f0 = __half22float2(m0);
        float2 f1 = __half22float2(m1);
        acc[c]     += f0.x + wy * (f0.y - f0.x);
        acc[4 + c] += f1.x + wy * (f1.y - f1.x);
    }
}

// Coarse gather: 4 threads/point, thread t owns channels [8t,8t+8), out [0,32).
__global__ void __launch_bounds__(256)
gather_coarse_kernel(const float* __restrict__ pts, float* __restrict__ out,
                     int n) {
    long tid = (long)blockIdx.x * blockDim.x + threadIdx.x;
    int p = (int)(tid >> 2);
    int t = (int)(tid & 3);
    if (p >= n) return;

    float x = __ldg(pts + (long)p * 3 + 0);
    float y = __ldg(pts + (long)p * 3 + 1);
    float z = __ldg(pts + (long)p * 3 + 2);

    float a[8] = {0.f,0.f,0.f,0.f,0.f,0.f,0.f,0.f};
    sample_plane<R0_>((const uint4*)g_xy0, x, y, t, a);
    sample_plane<R0_>((const uint4*)g_xz0, x, z, t, a);
    sample_plane<R0_>((const uint4*)g_yz0, y, z, t, a);

    float4* o = (float4*)(out + (long)p * 64);
    o[2 * t]     = make_float4(a[0], a[1], a[2], a[3]);
    o[2 * t + 1] = make_float4(a[4], a[5], a[6], a[7]);
}

// Fine gather: 4 threads/point, writes out floats [32,64).
__global__ void __launch_bounds__(256)
gather_fine_kernel(const float* __restrict__ pts, float* __restrict__ out,
                   int n) {
    long tid = (long)blockIdx.x * blockDim.x + threadIdx.x;
    int p = (int)(tid >> 2);
    int t = (int)(tid & 3);
    if (p >= n) return;

    float x = __ldg(pts + (long)p * 3 + 0);
    float y = __ldg(pts + (long)p * 3 + 1);
    float z = __ldg(pts + (long)p * 3 + 2);

    float a[8] = {0.f,0.f,0.f,0.f,0.f,0.f,0.f,0.f};
    sample_plane<R1_>((const uint4*)g_xy1, x, y, t, a);
    sample_plane<R1_>((const uint4*)g_xz1, x, z, t, a);
    sample_plane<R1_>((const uint4*)g_yz1, y, z, t, a);

    float4* o = (float4*)(out + (long)p * 64);
    o[8 + 2 * t]     = make_float4(a[0], a[1], a[2], a[3]);
    o[8 + 2 * t + 1] = make_float4(a[4], a[5], a[6], a[7]);
}

extern "C" void kernel_launch(void* const* d_in, const int* in_sizes, int n_in,
                              void* d_out, int out_size) {
    const float* pts = (const float*)d_in[0];
    int n = in_sizes[0] / 3;

    dim3 tb(32, 8);
    transpose_all_kernel<<<KT_ALL, tb>>>(
        (const float*)d_in[1], (const float*)d_in[2], (const float*)d_in[3],
        (const float*)d_in[4], (const float*)d_in[5], (const float*)d_in[6]);

    int threads = 256;
    long total = (long)n * 4;
    int blocks = (int)((total + threads - 1) / threads);
    gather_fine_kernel<<<blocks, threads>>>(pts, (float*)d_out, n);
    gather_coarse_kernel<<<blocks, threads>>>(pts, (float*)d_out, n);
}